// round 9
// baseline (speedup 1.0000x reference)
#include <cuda_runtime.h>
#include <cuda_fp16.h>
#include <cstdint>

// CostVolume: cost[b,i,h,x] = (1/128) sum_c L[b,c,h,x]*R[b,c,h,x-i], 0 for x<i.
// b=8 c=128 h=96 w=320, 48 disp, fp32.
// v9: single-pass fp16 mma.sync.m16n8k16 (fp32 accum), K pipelined in 8 slices
// of 16 channels, register prefetch, 4 CTAs/SM (regs capped at 64).

#define BB 8
#define CH 128
#define HH 96
#define WW 320
#define MAXD 48
#define PLANE (HH*WW)

#define ROWB 256         // smem row bytes: 128 k-values * 2B
#define AF 0             // A fp16 tile: 64*256  = 16384
#define BF 16384         // B fp16 tile: 112*256 = 28672
#define SMEM_TOTAL 45056

// col-perm swizzle: bijective on consecutive-8 rows (ldmatrix) and on the
// STS lane groups used below (<=2-way conflicts)
__device__ __forceinline__ uint32_t gfun(uint32_t m){
    return ((((m>>2)&1)<<2) | ((((m>>1)^(m>>4))&1)<<1) | (((m^(m>>3))&1)));
}
__device__ __forceinline__ uint32_t smem_u32(const void* p){
    uint32_t a;
    asm("{ .reg .u64 t; cvta.to.shared.u64 t, %1; cvt.u32.u64 %0, t; }" : "=r"(a) : "l"(p));
    return a;
}
// pack (v0 -> low half, v1 -> high half) as fp16x2
__device__ __forceinline__ uint32_t cvt_f16x2(float v0, float v1){
    uint32_t r;
    asm("cvt.rn.f16x2.f32 %0, %1, %2;" : "=r"(r) : "f"(v1), "f"(v0));
    return r;
}
__device__ __forceinline__ void ldsm_x4(uint32_t* r, uint32_t addr){
    asm volatile("ldmatrix.sync.aligned.m8n8.x4.shared.b16 {%0,%1,%2,%3}, [%4];"
                 : "=r"(r[0]), "=r"(r[1]), "=r"(r[2]), "=r"(r[3]) : "r"(addr));
}
__device__ __forceinline__ void mma16816(float* c, const uint32_t* a, const uint32_t* b){
    asm volatile("mma.sync.aligned.m16n8k16.row.col.f32.f16.f16.f32 "
                 "{%0,%1,%2,%3}, {%4,%5,%6,%7}, {%8,%9}, {%0,%1,%2,%3};"
                 : "+f"(c[0]), "+f"(c[1]), "+f"(c[2]), "+f"(c[3])
                 : "r"(a[0]), "r"(a[1]), "r"(a[2]), "r"(a[3]), "r"(b[0]), "r"(b[1]));
}
__device__ __forceinline__ float4 zero4(){ return make_float4(0.f,0.f,0.f,0.f); }

__global__ __launch_bounds__(256, 4)
void costvol_v9_kernel(const float* __restrict__ L,
                       const float* __restrict__ R,
                       float* __restrict__ out)
{
    extern __shared__ char smem[];
    const uint32_t sb = smem_u32(smem);

    const int tid  = threadIdx.x;
    const int warp = tid >> 5;
    const int lane = tid & 31;

    const int xt = blockIdx.x % 5;
    const int bh = blockIdx.x / 5;
    const int h  = bh % HH;
    const int b  = bh / HH;
    const int X0 = 64 * xt;

    const float* Lbh = L + ((size_t)b * CH * HH + h) * WW;
    const float* Rbh = R + ((size_t)b * CH * HH + h) * WW;

    // ---- A convert task: kp = lane>>2 (0..7), m2 = 4*warp + (lane&3) ----
    const int kpA = lane >> 2;
    const int m2A = 4 * warp + (lane & 3);
    const float* pLa = Lbh + X0 + 2 * m2A;
    const uint32_t gA0 = gfun((uint32_t)(2 * m2A));
    const uint32_t gA1 = gfun((uint32_t)(2 * m2A + 1));
    const uint32_t offA0base = (uint32_t)(2*m2A)   * ROWB;
    const uint32_t offA1base = (uint32_t)(2*m2A+1) * ROWB;

    // ---- B convert task: 224 active threads: n4 = tid%28, kp = tid/28 ----
    const bool actB = (tid < 224);
    const int n4B = tid % 28;
    const int kpB = tid / 28;
    const int xrB = X0 - 48 + 4 * n4B;
    uint32_t gB[4];
    #pragma unroll
    for (int e = 0; e < 4; e++) gB[e] = gfun((uint32_t)(4*n4B + e));

    // ---- mma lane constants ----
    const int mt = warp >> 1, nh = warp & 1;
    const int m0 = 16 * mt;
    const int lg = lane >> 3, l8 = lane & 7;
    const int arow = m0 + l8 + ((lg & 1) ? 8 : 0);
    const int asel = lg >> 1;
    const uint32_t gArow = gfun((uint32_t)arow);
    const int colselB = (lane >> 3) & 1;
    int browv[2]; uint32_t gBrow[2];
    #pragma unroll
    for (int j = 0; j < 2; j++){
        int p = 2*mt + 4*nh + 2*j + ((lane >> 4) & 1);
        browv[j] = 8*p + (lane & 7);
        gBrow[j] = gfun((uint32_t)browv[j]);
    }

    float C[4][4];
    #pragma unroll
    for (int t = 0; t < 4; t++)
        #pragma unroll
        for (int f = 0; f < 4; f++) C[t][f] = 0.f;

    float2 fa, fb;
    float4 b0, b1;

    auto prefetch = [&](int kc){
        int c0a = 2 * (kc * 8 + kpA);
        fa = *(const float2*)(pLa + (size_t)c0a * PLANE);
        fb = *(const float2*)(pLa + (size_t)(c0a + 1) * PLANE);
        if (actB && xrB >= 0){
            int c0b = 2 * (kc * 8 + kpB);
            b0 = *(const float4*)(Rbh + (size_t)c0b * PLANE + xrB);
            b1 = *(const float4*)(Rbh + (size_t)(c0b + 1) * PLANE + xrB);
        } else { b0 = zero4(); b1 = zero4(); }
    };

    auto convert_sts = [&](int kc){
        {   // A: 2 words (m = 2m2A, 2m2A+1)
            uint32_t kpg = (uint32_t)(kc * 8 + kpA);
            uint32_t c16 = kpg >> 2, w4 = (kpg & 3) << 2;
            *(uint32_t*)(smem + AF + offA0base + ((c16 ^ gA0) << 4) + w4)
                = cvt_f16x2(fa.x, fb.x);
            *(uint32_t*)(smem + AF + offA1base + ((c16 ^ gA1) << 4) + w4)
                = cvt_f16x2(fa.y, fb.y);
        }
        if (actB){  // B: 4 words (n = 4n4B+e)
            uint32_t kpg = (uint32_t)(kc * 8 + kpB);
            uint32_t c16 = kpg >> 2, w4 = (kpg & 3) << 2;
            const float va[4] = {b0.x, b0.y, b0.z, b0.w};
            const float vb[4] = {b1.x, b1.y, b1.z, b1.w};
            #pragma unroll
            for (int e = 0; e < 4; e++){
                uint32_t n = (uint32_t)(4*n4B + e);
                uint32_t off = n * ROWB + ((c16 ^ gB[e]) << 4) + w4;
                *(uint32_t*)(smem + BF + off) = cvt_f16x2(va[e], vb[e]);
            }
        }
    };

    // ---- pipelined main loop: convert(kc) | prefetch(kc+1) | bar | mma(kc) ----
    prefetch(0);
    #pragma unroll 1
    for (int kc = 0; kc < 8; kc++){
        convert_sts(kc);
        if (kc < 7) prefetch(kc + 1);
        __syncthreads();                 // slice kc visible to all warps

        uint32_t colA = (uint32_t)(kc * 2 + asel);
        uint32_t aoff = (uint32_t)arow * ROWB + ((colA ^ gArow) << 4);
        uint32_t af[4];
        ldsm_x4(af, sb + AF + aoff);
        #pragma unroll
        for (int j = 0; j < 2; j++){
            uint32_t colB = (uint32_t)(kc * 2 + colselB);
            uint32_t boff = (uint32_t)browv[j] * ROWB + ((colB ^ gBrow[j]) << 4);
            uint32_t bf[4];
            ldsm_x4(bf, sb + BF + boff);
            mma16816(C[2*j],     af, bf);       // tn = 2j   (p = 2mt+4nh+2j)
            mma16816(C[2*j + 1], af, bf + 2);   // tn = 2j+1
        }
        // no 2nd barrier: next convert writes a disjoint k-slice
    }
    __syncthreads();                     // all mma done before Obuf overlays A

    // ---- band extract into Obuf[i][m] (stride 68), scale 1/128 ----
    float* Ob = (float*)smem;            // 48*68*4 = 13056 B
    const int r  = lane >> 2;
    const int cb = 2 * (lane & 3);
    const float scale = 1.0f / 128.0f;
    #pragma unroll
    for (int tn = 0; tn < 4; tn++){
        int p = 2*mt + 4*nh + tn;
        #pragma unroll
        for (int f = 0; f < 4; f++){
            int row  = r + ((f >= 2) ? 8 : 0);
            int col  = cb + (f & 1);
            int mloc = m0 + row;
            int n    = 8*p + col;
            int i    = mloc + 48 - n;
            if (i >= 0 && i < MAXD)
                Ob[i * 68 + mloc] = C[tn][f] * scale;
        }
    }
    __syncthreads();

    // ---- coalesced store: 48 rows x 64 floats ----
    float* ob = out + (((size_t)b * MAXD) * HH + h) * WW + X0;
    #pragma unroll
    for (int q = tid; q < MAXD * 16; q += 256){
        int i = q >> 4, c4 = q & 15;
        float4 v = *(const float4*)(Ob + i * 68 + 4 * c4);
        *(float4*)(ob + (size_t)i * PLANE + 4 * c4) = v;
    }
}

extern "C" void kernel_launch(void* const* d_in, const int* in_sizes, int n_in,
                              void* d_out, int out_size)
{
    const float* L = (const float*)d_in[0];
    const float* R = (const float*)d_in[1];
    float* out = (float*)d_out;

    cudaFuncSetAttribute(costvol_v9_kernel,
                         cudaFuncAttributeMaxDynamicSharedMemorySize, SMEM_TOTAL);
    dim3 grid(BB * HH * 5);   // 3840 CTAs: (b, h, x-tile of 64)
    costvol_v9_kernel<<<grid, 256, SMEM_TOTAL>>>(L, R, out);
}